// round 12
// baseline (speedup 1.0000x reference)
#include <cuda_runtime.h>
#include <cuda_bf16.h>
#include <cuda_fp8.h>
#include <cstdint>

// ---------------------------------------------------------------------------
// DeepFM: out = bias + first + second + MLP(emb)
// FP8 e4m3 mma.sync GEMMs, CTA 128x128, BK=64, NS=4, **512 threads**
// (16 warps, warp tile 32x32) x 2 CTA/SM = 32 warps/SM for latency hiding.
// Fused weight-convert launch; G3 epilogue fuses h3 @ Wout.
// Scaling: act/weights fp8 of (value*64); acc = 4096*true. FM terms fp32.
// ---------------------------------------------------------------------------

namespace cfg {
constexpr int B  = 16384;
constexpr int F  = 26;
constexpr int V  = 100000;
constexpr int D  = 64;
constexpr int ND = 13;
constexpr int H1 = 1024;
constexpr int H2 = 512;
constexpr int H3 = 256;
constexpr int K0 = (F + 1) * D;   // 1728
}

constexpr float SCALE = 64.f;
constexpr float INV_SCALE = 1.f / 64.f;
constexpr float INV_SCALE2 = 1.f / 4096.f;

// ------------------------- scratch (device globals) ------------------------
__device__ uint8_t g_h  [(size_t)cfg::B * cfg::K0];   // fp8 e4m3, x64
__device__ uint8_t g_h1 [(size_t)cfg::B * cfg::H1];
__device__ uint8_t g_h2 [(size_t)cfg::B * cfg::H2];
__device__ uint8_t g_Wt1[cfg::H1 * cfg::K0];          // [N,K] fp8, x64
__device__ uint8_t g_Wt2[cfg::H2 * cfg::H1];
__device__ uint8_t g_Wt3[cfg::H3 * cfg::H2];

__device__ __forceinline__ uint8_t to_fp8(float v) {
    return (uint8_t)__nv_cvt_float_to_fp8(v, __NV_SATFINITE, __NV_E4M3);
}

// ------------------------- fused weight transpose+convert ------------------
__global__ __launch_bounds__(256) void transpose_convert_all(
    const float* __restrict__ W1, const float* __restrict__ W2,
    const float* __restrict__ W3) {
    const float* in;
    uint8_t* out;
    int K, N;
    if (blockIdx.z == 0)      { in = W1; out = g_Wt1; K = cfg::K0; N = cfg::H1; }
    else if (blockIdx.z == 1) { in = W2; out = g_Wt2; K = cfg::H1; N = cfg::H2; }
    else                      { in = W3; out = g_Wt3; K = cfg::H2; N = cfg::H3; }

    const int n0 = blockIdx.x * 32, k0 = blockIdx.y * 32;
    if (n0 >= N || k0 >= K) return;

    __shared__ float t[32][33];
    const int tx = threadIdx.x & 31, ty = threadIdx.x >> 5;  // 32x8
#pragma unroll
    for (int j = 0; j < 4; j++)
        t[ty + j * 8][tx] = in[(size_t)(k0 + ty + j * 8) * N + n0 + tx];
    __syncthreads();
#pragma unroll
    for (int j = 0; j < 4; j++)
        out[(size_t)(n0 + ty + j * 8) * K + k0 + tx] =
            to_fp8(t[tx][ty + j * 8] * SCALE);
}

// ------------------------- embed + FM (fp32 exact) -------------------------
__global__ __launch_bounds__(256) void embed_kernel(
    const float* __restrict__ dense, const int* __restrict__ sidx,
    const float* __restrict__ bias, const float* __restrict__ emb_tables,
    const float* __restrict__ lin_tables, const float* __restrict__ Wd,
    const float* __restrict__ Wld, const float* __restrict__ bld,
    float* __restrict__ out) {
    const int sub = threadIdx.x >> 6;
    const int d   = threadIdx.x & 63;
    const int row = blockIdx.x * 4 + sub;

    const float* dr = dense + (size_t)row * cfg::ND;

    int idx[cfg::F];
#pragma unroll
    for (int f = 0; f < cfg::F; f++) idx[f] = __ldg(sidx + (size_t)row * cfg::F + f);

    float ev[cfg::F];
#pragma unroll
    for (int f = 0; f < cfg::F; f++)
        ev[f] = __ldg(emb_tables + ((size_t)f * cfg::V + idx[f]) * cfg::D + d);

    float lin = 0.f;
    if (d < cfg::F) lin = __ldg(lin_tables + (size_t)d * cfg::V + idx[d]);

    float de = 0.f;
#pragma unroll
    for (int i = 0; i < cfg::ND; i++) de += dr[i] * Wd[i * cfg::D + d];

    float s  = de;
    float sq = de * de;
    uint8_t* hrow = g_h + (size_t)row * cfg::K0;
    hrow[d] = to_fp8(de * SCALE);

#pragma unroll
    for (int f = 0; f < cfg::F; f++) {
        float e = ev[f];
        s  += e;
        sq += e * e;
        hrow[(size_t)(f + 1) * cfg::D + d] = to_fp8(e * SCALE);
    }

    float val = 0.5f * (s * s - sq) + lin;
    if (d < cfg::ND) val += dr[d] * Wld[d];

#pragma unroll
    for (int o = 16; o > 0; o >>= 1)
        val += __shfl_down_sync(0xffffffffu, val, o);

    __shared__ float red[8];
    if ((threadIdx.x & 31) == 0) red[threadIdx.x >> 5] = val;
    __syncthreads();
    if (d == 0)
        out[row] = bias[0] + bld[0] + red[sub * 2] + red[sub * 2 + 1];
}

// ------------------------- FP8 tensor-core GEMM ----------------------------
// CTA 128x128, 16 warps (4M x 4N), warp tile 32x32, BK=64, NS=4 stages.
#define BM 128
#define BN 128
#define BK 64
#define NS 4
#define TSTR 80                     // 64B row + 16B pad (conflict-free)
#define A_ST (BM * TSTR)            // 10240 B / stage
#define B_ST (BN * TSTR)            // 10240 B / stage
#define STAGE_B (A_ST + B_ST)
#define GEMM_SMEM (NS * STAGE_B)    // 81920 B

__device__ __forceinline__ uint32_t smem_u32(const void* p) {
    return (uint32_t)__cvta_generic_to_shared(p);
}
__device__ __forceinline__ void cp16(uint32_t s, const void* g) {
    asm volatile("cp.async.cg.shared.global [%0], [%1], 16;\n" ::"r"(s), "l"(g));
}
__device__ __forceinline__ void cp_commit() {
    asm volatile("cp.async.commit_group;\n");
}
template <int N> __device__ __forceinline__ void cp_wait() {
    asm volatile("cp.async.wait_group %0;\n" ::"n"(N));
}
__device__ __forceinline__ void ldm_x4(uint32_t a, uint32_t& r0, uint32_t& r1,
                                       uint32_t& r2, uint32_t& r3) {
    asm volatile("ldmatrix.sync.aligned.m8n8.x4.shared.b16 {%0,%1,%2,%3}, [%4];\n"
                 : "=r"(r0), "=r"(r1), "=r"(r2), "=r"(r3)
                 : "r"(a));
}
__device__ __forceinline__ void mma_fp8(float* c, const uint32_t* a,
                                        uint32_t b0, uint32_t b1) {
    asm volatile(
        "mma.sync.aligned.m16n8k32.row.col.f32.e4m3.e4m3.f32 "
        "{%0,%1,%2,%3}, {%4,%5,%6,%7}, {%8,%9}, {%0,%1,%2,%3};\n"
        : "+f"(c[0]), "+f"(c[1]), "+f"(c[2]), "+f"(c[3])
        : "r"(a[0]), "r"(a[1]), "r"(a[2]), "r"(a[3]), "r"(b0), "r"(b1));
}

// MODE 0: C = fp8(relu(acc)/64).  MODE 1: out[m] += relu(acc)@Wout/4096.
template <int MODE>
__global__ __launch_bounds__(512, 2) void gemm_relu_fp8(
    const uint8_t* __restrict__ A, const uint8_t* __restrict__ Wt,
    uint8_t* __restrict__ C, const float* __restrict__ Wout,
    float* __restrict__ out, int M, int N, int K)
{
    extern __shared__ __align__(16) uint8_t smem[];

    const int tid  = threadIdx.x;
    const int bm   = blockIdx.y * BM;
    const int bn   = blockIdx.x * BN;
    const int wid  = tid >> 5;
    const int lane = tid & 31;
    const int wm   = (wid & 3) * 32;   // 4 warps over M
    const int wn   = (wid >> 2) * 32;  // 4 warps over N

    // ---- per-thread load addresses: one A + one B cp16 per stage ----
    const int r0  = tid >> 2;           // 0..127
    const int cg0 = (tid & 3) * 16;     // 0/16/32/48
    const uint8_t* pA = A  + (size_t)(bm + r0) * K + cg0;
    const uint8_t* pB = Wt + (size_t)(bn + r0) * K + cg0;
    const uint32_t sbase = smem_u32(smem);
    const uint32_t sAoff = sbase + r0 * TSTR + cg0;
    const uint32_t sBoff = sAoff + A_ST;

    auto load_tiles = [&](int buf, const uint8_t* a, const uint8_t* b) {
        const uint32_t so = buf * STAGE_B;
        cp16(sAoff + so, a);
        cp16(sBoff + so, b);
    };

    // ---- per-warp ldmatrix smem bases ----
    const uint32_t aBase = sbase + (wm + (lane & 15)) * TSTR +
                           (lane >> 4) * 16;
    const uint32_t bBase = sbase + A_ST + (wn + (lane & 15)) * TSTR +
                           (lane >> 4) * 16;

    float acc[2][4][4];
#pragma unroll
    for (int i = 0; i < 2; i++)
#pragma unroll
        for (int j = 0; j < 4; j++)
#pragma unroll
            for (int k = 0; k < 4; k++) acc[i][j][k] = 0.f;

    const int KT = K / BK;

#pragma unroll
    for (int s = 0; s < NS - 1; s++) {
        load_tiles(s, pA, pB);
        pA += BK;
        pB += BK;
        cp_commit();
    }

    for (int kt = 0; kt < KT; kt++) {
        const int buf = kt % NS;
        cp_wait<NS - 2>();
        __syncthreads();

        if (kt + NS - 1 < KT) {
            load_tiles((kt + NS - 1) % NS, pA, pB);
            pA += BK;
            pB += BK;
        }
        cp_commit();

        const uint32_t so = buf * STAGE_B;

        // ---- all fragment loads for both k32 steps first ----
        uint32_t af[2][2][4], bf[2][2][4];
#pragma unroll
        for (int ks = 0; ks < 2; ks++) {
            const uint32_t kso = so + ks * 32;
#pragma unroll
            for (int mi = 0; mi < 2; mi++)
                ldm_x4(aBase + kso + mi * (16 * TSTR),
                       af[ks][mi][0], af[ks][mi][1],
                       af[ks][mi][2], af[ks][mi][3]);
#pragma unroll
            for (int nj = 0; nj < 2; nj++)
                ldm_x4(bBase + kso + nj * (16 * TSTR),
                       bf[ks][nj][0], bf[ks][nj][1],
                       bf[ks][nj][2], bf[ks][nj][3]);
        }
        // ---- then all 16 mma ----
#pragma unroll
        for (int ks = 0; ks < 2; ks++)
#pragma unroll
            for (int mi = 0; mi < 2; mi++)
#pragma unroll
                for (int nj = 0; nj < 2; nj++) {
                    mma_fp8(acc[mi][nj * 2],     af[ks][mi],
                            bf[ks][nj][0], bf[ks][nj][2]);
                    mma_fp8(acc[mi][nj * 2 + 1], af[ks][mi],
                            bf[ks][nj][1], bf[ks][nj][3]);
                }
    }

    const int lr = lane >> 2, lc = (lane & 3) * 2;
    if (MODE == 1) {
        // out[m] += relu(acc) @ Wout / 4096
#pragma unroll
        for (int mi = 0; mi < 2; mi++) {
            float s0 = 0.f, s1 = 0.f;
#pragma unroll
            for (int ni = 0; ni < 4; ni++) {
                int n0 = bn + wn + ni * 8 + lc;
                float w0 = __ldg(Wout + n0);
                float w1 = __ldg(Wout + n0 + 1);
                s0 += fmaxf(acc[mi][ni][0], 0.f) * w0 +
                      fmaxf(acc[mi][ni][1], 0.f) * w1;
                s1 += fmaxf(acc[mi][ni][2], 0.f) * w0 +
                      fmaxf(acc[mi][ni][3], 0.f) * w1;
            }
            s0 += __shfl_xor_sync(0xffffffffu, s0, 1);
            s0 += __shfl_xor_sync(0xffffffffu, s0, 2);
            s1 += __shfl_xor_sync(0xffffffffu, s1, 1);
            s1 += __shfl_xor_sync(0xffffffffu, s1, 2);
            if ((lane & 3) == 0) {
                int m0 = bm + wm + mi * 16 + lr;
                atomicAdd(out + m0,     s0 * INV_SCALE2);
                atomicAdd(out + m0 + 8, s1 * INV_SCALE2);
            }
        }
    } else {
#pragma unroll
        for (int mi = 0; mi < 2; mi++)
#pragma unroll
            for (int ni = 0; ni < 4; ni++) {
                int m0 = bm + wm + mi * 16 + lr;
                int n0 = bn + wn + ni * 8 + lc;
                float v0 = fmaxf(acc[mi][ni][0], 0.f) * INV_SCALE;
                float v1 = fmaxf(acc[mi][ni][1], 0.f) * INV_SCALE;
                float v2 = fmaxf(acc[mi][ni][2], 0.f) * INV_SCALE;
                float v3 = fmaxf(acc[mi][ni][3], 0.f) * INV_SCALE;
                *reinterpret_cast<unsigned short*>(C + (size_t)m0 * N + n0) =
                    (unsigned short)__nv_cvt_float2_to_fp8x2(
                        make_float2(v0, v1), __NV_SATFINITE, __NV_E4M3);
                *reinterpret_cast<unsigned short*>(C + (size_t)(m0 + 8) * N + n0) =
                    (unsigned short)__nv_cvt_float2_to_fp8x2(
                        make_float2(v2, v3), __NV_SATFINITE, __NV_E4M3);
            }
    }
}

// ------------------------- launch ------------------------------------------
extern "C" void kernel_launch(void* const* d_in, const int* in_sizes, int n_in,
                              void* d_out, int out_size) {
    const float* dense = (const float*)d_in[0];
    const int*   sidx  = (const int*)d_in[1];
    const float* bias  = (const float*)d_in[2];
    const float* emb   = (const float*)d_in[3];
    const float* lin   = (const float*)d_in[4];
    const float* Wd    = (const float*)d_in[5];
    const float* Wld   = (const float*)d_in[6];
    const float* bld   = (const float*)d_in[7];
    const float* W1    = (const float*)d_in[8];
    const float* W2    = (const float*)d_in[9];
    const float* W3    = (const float*)d_in[10];
    const float* Wout  = (const float*)d_in[11];
    float* out = (float*)d_out;

    void *p_h, *p_h1, *p_h2, *p_W1, *p_W2, *p_W3;
    cudaGetSymbolAddress(&p_h,  g_h);
    cudaGetSymbolAddress(&p_h1, g_h1);
    cudaGetSymbolAddress(&p_h2, g_h2);
    cudaGetSymbolAddress(&p_W1, g_Wt1);
    cudaGetSymbolAddress(&p_W2, g_Wt2);
    cudaGetSymbolAddress(&p_W3, g_Wt3);

    static bool attr_done = false;
    if (!attr_done) {
        cudaFuncSetAttribute(gemm_relu_fp8<0>,
                             cudaFuncAttributeMaxDynamicSharedMemorySize,
                             GEMM_SMEM);
        cudaFuncSetAttribute(gemm_relu_fp8<1>,
                             cudaFuncAttributeMaxDynamicSharedMemorySize,
                             GEMM_SMEM);
        attr_done = true;
    }

    transpose_convert_all<<<dim3(cfg::H1 / 32, cfg::K0 / 32, 3), 256>>>(
        W1, W2, W3);

    embed_kernel<<<cfg::B / 4, 256>>>(dense, sidx, bias, emb, lin, Wd, Wld,
                                      bld, out);

    dim3 g1(cfg::H1 / BN, cfg::B / BM);
    gemm_relu_fp8<0><<<g1, 512, GEMM_SMEM>>>(
        (const uint8_t*)p_h, (const uint8_t*)p_W1, (uint8_t*)p_h1,
        nullptr, nullptr, cfg::B, cfg::H1, cfg::K0);
    dim3 g2(cfg::H2 / BN, cfg::B / BM);
    gemm_relu_fp8<0><<<g2, 512, GEMM_SMEM>>>(
        (const uint8_t*)p_h1, (const uint8_t*)p_W2, (uint8_t*)p_h2,
        nullptr, nullptr, cfg::B, cfg::H2, cfg::H1);
    dim3 g3(cfg::H3 / BN, cfg::B / BM);
    gemm_relu_fp8<1><<<g3, 512, GEMM_SMEM>>>(
        (const uint8_t*)p_h2, (const uint8_t*)p_W3, nullptr,
        Wout, out, cfg::B, cfg::H3, cfg::H2);
}

// round 13
// speedup vs baseline: 1.1595x; 1.1595x over previous
#include <cuda_runtime.h>
#include <cuda_bf16.h>
#include <cuda_fp8.h>
#include <cstdint>

// ---------------------------------------------------------------------------
// DeepFM: out = bias + first + second + MLP(emb)
// FP8 e4m3 mma.sync GEMMs, CTA 128x128, BK=64, NS=4, 256 thr, 2 CTA/SM.
// R13: loop restructured so each iteration starts with ldmatrix on a stage
// that the PREVIOUS iteration's cp_wait+barrier already published; the
// barrier at the end of the body hides under the in-flight mma work.
// Fused weight-convert launch; G3 epilogue fuses h3 @ Wout.
// Scaling: act/weights fp8 of (value*64); acc = 4096*true. FM terms fp32.
// ---------------------------------------------------------------------------

namespace cfg {
constexpr int B  = 16384;
constexpr int F  = 26;
constexpr int V  = 100000;
constexpr int D  = 64;
constexpr int ND = 13;
constexpr int H1 = 1024;
constexpr int H2 = 512;
constexpr int H3 = 256;
constexpr int K0 = (F + 1) * D;   // 1728
}

constexpr float SCALE = 64.f;
constexpr float INV_SCALE = 1.f / 64.f;
constexpr float INV_SCALE2 = 1.f / 4096.f;

// ------------------------- scratch (device globals) ------------------------
__device__ uint8_t g_h  [(size_t)cfg::B * cfg::K0];   // fp8 e4m3, x64
__device__ uint8_t g_h1 [(size_t)cfg::B * cfg::H1];
__device__ uint8_t g_h2 [(size_t)cfg::B * cfg::H2];
__device__ uint8_t g_Wt1[cfg::H1 * cfg::K0];          // [N,K] fp8, x64
__device__ uint8_t g_Wt2[cfg::H2 * cfg::H1];
__device__ uint8_t g_Wt3[cfg::H3 * cfg::H2];

__device__ __forceinline__ uint8_t to_fp8(float v) {
    return (uint8_t)__nv_cvt_float_to_fp8(v, __NV_SATFINITE, __NV_E4M3);
}

// ------------------------- fused weight transpose+convert ------------------
__global__ __launch_bounds__(256) void transpose_convert_all(
    const float* __restrict__ W1, const float* __restrict__ W2,
    const float* __restrict__ W3) {
    const float* in;
    uint8_t* out;
    int K, N;
    if (blockIdx.z == 0)      { in = W1; out = g_Wt1; K = cfg::K0; N = cfg::H1; }
    else if (blockIdx.z == 1) { in = W2; out = g_Wt2; K = cfg::H1; N = cfg::H2; }
    else                      { in = W3; out = g_Wt3; K = cfg::H2; N = cfg::H3; }

    const int n0 = blockIdx.x * 32, k0 = blockIdx.y * 32;
    if (n0 >= N || k0 >= K) return;

    __shared__ float t[32][33];
    const int tx = threadIdx.x & 31, ty = threadIdx.x >> 5;  // 32x8
#pragma unroll
    for (int j = 0; j < 4; j++)
        t[ty + j * 8][tx] = in[(size_t)(k0 + ty + j * 8) * N + n0 + tx];
    __syncthreads();
#pragma unroll
    for (int j = 0; j < 4; j++)
        out[(size_t)(n0 + ty + j * 8) * K + k0 + tx] =
            to_fp8(t[tx][ty + j * 8] * SCALE);
}

// ------------------------- embed + FM (fp32 exact) -------------------------
__global__ __launch_bounds__(256) void embed_kernel(
    const float* __restrict__ dense, const int* __restrict__ sidx,
    const float* __restrict__ bias, const float* __restrict__ emb_tables,
    const float* __restrict__ lin_tables, const float* __restrict__ Wd,
    const float* __restrict__ Wld, const float* __restrict__ bld,
    float* __restrict__ out) {
    const int sub = threadIdx.x >> 6;
    const int d   = threadIdx.x & 63;
    const int row = blockIdx.x * 4 + sub;

    const float* dr = dense + (size_t)row * cfg::ND;

    int idx[cfg::F];
#pragma unroll
    for (int f = 0; f < cfg::F; f++) idx[f] = __ldg(sidx + (size_t)row * cfg::F + f);

    float ev[cfg::F];
#pragma unroll
    for (int f = 0; f < cfg::F; f++)
        ev[f] = __ldg(emb_tables + ((size_t)f * cfg::V + idx[f]) * cfg::D + d);

    float lin = 0.f;
    if (d < cfg::F) lin = __ldg(lin_tables + (size_t)d * cfg::V + idx[d]);

    float de = 0.f;
#pragma unroll
    for (int i = 0; i < cfg::ND; i++) de += dr[i] * Wd[i * cfg::D + d];

    float s  = de;
    float sq = de * de;
    uint8_t* hrow = g_h + (size_t)row * cfg::K0;
    hrow[d] = to_fp8(de * SCALE);

#pragma unroll
    for (int f = 0; f < cfg::F; f++) {
        float e = ev[f];
        s  += e;
        sq += e * e;
        hrow[(size_t)(f + 1) * cfg::D + d] = to_fp8(e * SCALE);
    }

    float val = 0.5f * (s * s - sq) + lin;
    if (d < cfg::ND) val += dr[d] * Wld[d];

#pragma unroll
    for (int o = 16; o > 0; o >>= 1)
        val += __shfl_down_sync(0xffffffffu, val, o);

    __shared__ float red[8];
    if ((threadIdx.x & 31) == 0) red[threadIdx.x >> 5] = val;
    __syncthreads();
    if (d == 0)
        out[row] = bias[0] + bld[0] + red[sub * 2] + red[sub * 2 + 1];
}

// ------------------------- FP8 tensor-core GEMM ----------------------------
// CTA 128x128, 8 warps (4M x 2N), warp tile 32x64, BK=64, NS=4 stages.
#define BM 128
#define BN 128
#define BK 64
#define NS 4
#define TSTR 80                     // 64B row + 16B pad (conflict-free)
#define A_ST (BM * TSTR)            // 10240 B / stage
#define B_ST (BN * TSTR)            // 10240 B / stage
#define STAGE_B (A_ST + B_ST)
#define GEMM_SMEM (NS * STAGE_B)    // 81920 B

__device__ __forceinline__ uint32_t smem_u32(const void* p) {
    return (uint32_t)__cvta_generic_to_shared(p);
}
__device__ __forceinline__ void cp16(uint32_t s, const void* g) {
    asm volatile("cp.async.cg.shared.global [%0], [%1], 16;\n" ::"r"(s), "l"(g));
}
__device__ __forceinline__ void cp_commit() {
    asm volatile("cp.async.commit_group;\n");
}
template <int N> __device__ __forceinline__ void cp_wait() {
    asm volatile("cp.async.wait_group %0;\n" ::"n"(N));
}
__device__ __forceinline__ void ldm_x4(uint32_t a, uint32_t& r0, uint32_t& r1,
                                       uint32_t& r2, uint32_t& r3) {
    asm volatile("ldmatrix.sync.aligned.m8n8.x4.shared.b16 {%0,%1,%2,%3}, [%4];\n"
                 : "=r"(r0), "=r"(r1), "=r"(r2), "=r"(r3)
                 : "r"(a));
}
__device__ __forceinline__ void mma_fp8(float* c, const uint32_t* a,
                                        uint32_t b0, uint32_t b1) {
    asm volatile(
        "mma.sync.aligned.m16n8k32.row.col.f32.e4m3.e4m3.f32 "
        "{%0,%1,%2,%3}, {%4,%5,%6,%7}, {%8,%9}, {%0,%1,%2,%3};\n"
        : "+f"(c[0]), "+f"(c[1]), "+f"(c[2]), "+f"(c[3])
        : "r"(a[0]), "r"(a[1]), "r"(a[2]), "r"(a[3]), "r"(b0), "r"(b1));
}

// MODE 0: C = fp8(relu(acc)/64).  MODE 1: out[m] += relu(acc)@Wout/4096.
template <int MODE>
__global__ __launch_bounds__(256, 2) void gemm_relu_fp8(
    const uint8_t* __restrict__ A, const uint8_t* __restrict__ Wt,
    uint8_t* __restrict__ C, const float* __restrict__ Wout,
    float* __restrict__ out, int M, int N, int K)
{
    extern __shared__ __align__(16) uint8_t smem[];

    const int tid  = threadIdx.x;
    const int bm   = blockIdx.y * BM;
    const int bn   = blockIdx.x * BN;
    const int wid  = tid >> 5;
    const int lane = tid & 31;
    const int wm   = (wid & 3) * 32;   // 4 warps over M
    const int wn   = (wid >> 2) * 64;  // 2 warps over N

    // ---- persistent per-thread load addresses (advance by BK per stage) ----
    const int r0  = tid >> 2;           // 0..63
    const int cg0 = (tid & 3) * 16;     // 0/16/32/48
    const uint8_t* pA = A  + (size_t)(bm + r0) * K + cg0;
    const uint8_t* pB = Wt + (size_t)(bn + r0) * K + cg0;
    const size_t rowstep = (size_t)64 * K;    // +64 rows
    const uint32_t sbase = smem_u32(smem);
    const uint32_t sAoff = sbase + r0 * TSTR + cg0;
    const uint32_t sBoff = sAoff + A_ST;

    auto load_tiles = [&](int buf, const uint8_t* a, const uint8_t* b) {
        const uint32_t so = buf * STAGE_B;
        cp16(sAoff + so,             a);
        cp16(sAoff + so + 64 * TSTR, a + rowstep);
        cp16(sBoff + so,             b);
        cp16(sBoff + so + 64 * TSTR, b + rowstep);
    };

    // ---- per-warp ldmatrix smem bases ----
    const uint32_t aBase = sbase + (wm + (lane & 15)) * TSTR +
                           (lane >> 4) * 16;
    const uint32_t bBase = sbase + A_ST + (wn + (lane & 15)) * TSTR +
                           (lane >> 4) * 16;

    float acc[2][8][4];
#pragma unroll
    for (int i = 0; i < 2; i++)
#pragma unroll
        for (int j = 0; j < 8; j++)
#pragma unroll
            for (int k = 0; k < 4; k++) acc[i][j][k] = 0.f;

    const int KT = K / BK;

    // prologue: stages 0..NS-2 in flight; stage 0 completed + published
#pragma unroll
    for (int s = 0; s < NS - 1; s++) {
        load_tiles(s, pA, pB);
        pA += BK;
        pB += BK;
        cp_commit();
    }
    cp_wait<NS - 2>();
    __syncthreads();

    for (int kt = 0; kt < KT; kt++) {
        const uint32_t so = (kt % NS) * STAGE_B;

        // ---- stage kt is already complete AND barrier-published: load frags
        uint32_t af[2][2][4], bf[2][4][4];
#pragma unroll
        for (int ks = 0; ks < 2; ks++) {
            const uint32_t kso = so + ks * 32;
#pragma unroll
            for (int mi = 0; mi < 2; mi++)
                ldm_x4(aBase + kso + mi * (16 * TSTR),
                       af[ks][mi][0], af[ks][mi][1],
                       af[ks][mi][2], af[ks][mi][3]);
#pragma unroll
            for (int nj = 0; nj < 4; nj++)
                ldm_x4(bBase + kso + nj * (16 * TSTR),
                       bf[ks][nj][0], bf[ks][nj][1],
                       bf[ks][nj][2], bf[ks][nj][3]);
        }

        // ---- issue next-stage global loads into the slot consumed at kt-1
        if (kt + NS - 1 < KT) {
            load_tiles((kt + NS - 1) % NS, pA, pB);
            pA += BK;
            pB += BK;
        }
        cp_commit();   // unconditional: keep group-count invariant

        // ---- all 32 mma (tensor pipe busy while we then wait/barrier) ----
#pragma unroll
        for (int ks = 0; ks < 2; ks++)
#pragma unroll
            for (int mi = 0; mi < 2; mi++)
#pragma unroll
                for (int nj = 0; nj < 4; nj++) {
                    mma_fp8(acc[mi][nj * 2],     af[ks][mi],
                            bf[ks][nj][0], bf[ks][nj][2]);
                    mma_fp8(acc[mi][nj * 2 + 1], af[ks][mi],
                            bf[ks][nj][1], bf[ks][nj][3]);
                }

        // ---- publish stage kt+1 for the next iteration; protect the slot
        //      (kt)%NS from being overwritten before all warps read it ----
        cp_wait<NS - 2>();
        __syncthreads();
    }

    const int lr = lane >> 2, lc = (lane & 3) * 2;
    if (MODE == 1) {
        // out[m] += relu(acc) @ Wout / 4096
#pragma unroll
        for (int mi = 0; mi < 2; mi++) {
            float s0 = 0.f, s1 = 0.f;
#pragma unroll
            for (int ni = 0; ni < 8; ni++) {
                int n0 = bn + wn + ni * 8 + lc;
                float w0 = __ldg(Wout + n0);
                float w1 = __ldg(Wout + n0 + 1);
                s0 += fmaxf(acc[mi][ni][0], 0.f) * w0 +
                      fmaxf(acc[mi][ni][1], 0.f) * w1;
                s1 += fmaxf(acc[mi][ni][2], 0.f) * w0 +
                      fmaxf(acc[mi][ni][3], 0.f) * w1;
            }
            s0 += __shfl_xor_sync(0xffffffffu, s0, 1);
            s0 += __shfl_xor_sync(0xffffffffu, s0, 2);
            s1 += __shfl_xor_sync(0xffffffffu, s1, 1);
            s1 += __shfl_xor_sync(0xffffffffu, s1, 2);
            if ((lane & 3) == 0) {
                int m0 = bm + wm + mi * 16 + lr;
                atomicAdd(out + m0,     s0 * INV_SCALE2);
                atomicAdd(out + m0 + 8, s1 * INV_SCALE2);
            }
        }
    } else {
#pragma unroll
        for (int mi = 0; mi < 2; mi++)
#pragma unroll
            for (int ni = 0; ni < 8; ni++) {
                int m0 = bm + wm + mi * 16 + lr;
                int n0 = bn + wn + ni * 8 + lc;
                float v0 = fmaxf(acc[mi][ni][0], 0.f) * INV_SCALE;
                float v1 = fmaxf(acc[mi][ni][1], 0.f) * INV_SCALE;
                float v2 = fmaxf(acc[mi][ni][2], 0.f) * INV_SCALE;
                float v3 = fmaxf(acc[mi][ni][3], 0.f) * INV_SCALE;
                *reinterpret_cast<unsigned short*>(C + (size_t)m0 * N + n0) =
                    (unsigned short)__nv_cvt_float2_to_fp8x2(
                        make_float2(v0, v1), __NV_SATFINITE, __NV_E4M3);
                *reinterpret_cast<unsigned short*>(C + (size_t)(m0 + 8) * N + n0) =
                    (unsigned short)__nv_cvt_float2_to_fp8x2(
                        make_float2(v2, v3), __NV_SATFINITE, __NV_E4M3);
            }
    }
}

// ------------------------- launch ------------------------------------------
extern "C" void kernel_launch(void* const* d_in, const int* in_sizes, int n_in,
                              void* d_out, int out_size) {
    const float* dense = (const float*)d_in[0];
    const int*   sidx  = (const int*)d_in[1];
    const float* bias  = (const float*)d_in[2];
    const float* emb   = (const float*)d_in[3];
    const float* lin   = (const float*)d_in[4];
    const float* Wd    = (const float*)d_in[5];
    const float* Wld   = (const float*)d_in[6];
    const float* bld   = (const float*)d_in[7];
    const float* W1    = (const float*)d_in[8];
    const float* W2    = (const float*)d_in[9];
    const float* W3    = (const float*)d_in[10];
    const float* Wout  = (const float*)d_in[11];
    float* out = (float*)d_out;

    void *p_h, *p_h1, *p_h2, *p_W1, *p_W2, *p_W3;
    cudaGetSymbolAddress(&p_h,  g_h);
    cudaGetSymbolAddress(&p_h1, g_h1);
    cudaGetSymbolAddress(&p_h2, g_h2);
    cudaGetSymbolAddress(&p_W1, g_Wt1);
    cudaGetSymbolAddress(&p_W2, g_Wt2);
    cudaGetSymbolAddress(&p_W3, g_Wt3);

    static bool attr_done = false;
    if (!attr_done) {
        cudaFuncSetAttribute(gemm_relu_fp8<0>,
                             cudaFuncAttributeMaxDynamicSharedMemorySize,
                             GEMM_SMEM);
        cudaFuncSetAttribute(gemm_relu_fp8<1>,
                             cudaFuncAttributeMaxDynamicSharedMemorySize,
                             GEMM_SMEM);
        attr_done = true;
    }

    transpose_convert_all<<<dim3(cfg::H1 / 32, cfg::K0 / 32, 3), 256>>>(
        W1, W2, W3);

    embed_kernel<<<cfg::B / 4, 256>>>(dense, sidx, bias, emb, lin, Wd, Wld,
                                      bld, out);

    dim3 g1(cfg::H1 / BN, cfg::B / BM);
    gemm_relu_fp8<0><<<g1, 256, GEMM_SMEM>>>(
        (const uint8_t*)p_h, (const uint8_t*)p_W1, (uint8_t*)p_h1,
        nullptr, nullptr, cfg::B, cfg::H1, cfg::K0);
    dim3 g2(cfg::H2 / BN, cfg::B / BM);
    gemm_relu_fp8<0><<<g2, 256, GEMM_SMEM>>>(
        (const uint8_t*)p_h1, (const uint8_t*)p_W2, (uint8_t*)p_h2,
        nullptr, nullptr, cfg::B, cfg::H2, cfg::H1);
    dim3 g3(cfg::H3 / BN, cfg::B / BM);
    gemm_relu_fp8<1><<<g3, 256, GEMM_SMEM>>>(
        (const uint8_t*)p_h2, (const uint8_t*)p_W3, nullptr,
        Wout, out, cfg::B, cfg::H3, cfg::H2);
}

// round 14
// speedup vs baseline: 1.3680x; 1.1799x over previous
#include <cuda_runtime.h>
#include <cuda_bf16.h>
#include <cuda_fp8.h>
#include <cstdint>

// ---------------------------------------------------------------------------
// DeepFM: out = bias + first + second + MLP(emb)
// GEMM core = R11 champion verbatim (fp8 e4m3 mma.sync, CTA 128x128, BK=64,
// NS=4, 256 thr, 2 CTA/SM, fragment-prefetch body).
// R14: embed kernel uses float4 gathers + packed fp8x4 stores (16 lanes/row);
// weight-convert runs on a forked stream under embed.
// Scaling: act/weights fp8 of (value*64); acc = 4096*true. FM terms fp32.
// ---------------------------------------------------------------------------

namespace cfg {
constexpr int B  = 16384;
constexpr int F  = 26;
constexpr int V  = 100000;
constexpr int D  = 64;
constexpr int ND = 13;
constexpr int H1 = 1024;
constexpr int H2 = 512;
constexpr int H3 = 256;
constexpr int K0 = (F + 1) * D;   // 1728
}

constexpr float SCALE = 64.f;
constexpr float INV_SCALE = 1.f / 64.f;
constexpr float INV_SCALE2 = 1.f / 4096.f;

// ------------------------- scratch (device globals) ------------------------
__device__ uint8_t g_h  [(size_t)cfg::B * cfg::K0];   // fp8 e4m3, x64
__device__ uint8_t g_h1 [(size_t)cfg::B * cfg::H1];
__device__ uint8_t g_h2 [(size_t)cfg::B * cfg::H2];
__device__ uint8_t g_Wt1[cfg::H1 * cfg::K0];          // [N,K] fp8, x64
__device__ uint8_t g_Wt2[cfg::H2 * cfg::H1];
__device__ uint8_t g_Wt3[cfg::H3 * cfg::H2];

__device__ __forceinline__ uint8_t to_fp8(float v) {
    return (uint8_t)__nv_cvt_float_to_fp8(v, __NV_SATFINITE, __NV_E4M3);
}
__device__ __forceinline__ uint32_t pack4_fp8(float a, float b, float c,
                                              float d) {
    uint32_t lo = (uint32_t)__nv_cvt_float2_to_fp8x2(
        make_float2(a, b), __NV_SATFINITE, __NV_E4M3);
    uint32_t hi = (uint32_t)__nv_cvt_float2_to_fp8x2(
        make_float2(c, d), __NV_SATFINITE, __NV_E4M3);
    return lo | (hi << 16);
}

// ------------------------- fused weight transpose+convert ------------------
__global__ __launch_bounds__(256) void transpose_convert_all(
    const float* __restrict__ W1, const float* __restrict__ W2,
    const float* __restrict__ W3) {
    const float* in;
    uint8_t* out;
    int K, N;
    if (blockIdx.z == 0)      { in = W1; out = g_Wt1; K = cfg::K0; N = cfg::H1; }
    else if (blockIdx.z == 1) { in = W2; out = g_Wt2; K = cfg::H1; N = cfg::H2; }
    else                      { in = W3; out = g_Wt3; K = cfg::H2; N = cfg::H3; }

    const int n0 = blockIdx.x * 32, k0 = blockIdx.y * 32;
    if (n0 >= N || k0 >= K) return;

    __shared__ float t[32][33];
    const int tx = threadIdx.x & 31, ty = threadIdx.x >> 5;  // 32x8
#pragma unroll
    for (int j = 0; j < 4; j++)
        t[ty + j * 8][tx] = in[(size_t)(k0 + ty + j * 8) * N + n0 + tx];
    __syncthreads();
#pragma unroll
    for (int j = 0; j < 4; j++)
        out[(size_t)(n0 + ty + j * 8) * K + k0 + tx] =
            to_fp8(t[tx][ty + j * 8] * SCALE);
}

// ------------------------- embed + FM (fp32 exact, float4 lanes) -----------
// 256 threads = 16 rows x 16 lanes; lane q owns d = 4q..4q+3.
__global__ __launch_bounds__(256) void embed_kernel(
    const float* __restrict__ dense, const int* __restrict__ sidx,
    const float* __restrict__ bias, const float* __restrict__ emb_tables,
    const float* __restrict__ lin_tables, const float* __restrict__ Wd,
    const float* __restrict__ Wld, const float* __restrict__ bld,
    float* __restrict__ out) {
    const int q   = threadIdx.x & 15;          // d-quad
    const int row = blockIdx.x * 16 + (threadIdx.x >> 4);

    const float* dr = dense + (size_t)row * cfg::ND;

    int idx[cfg::F];
#pragma unroll
    for (int f = 0; f < cfg::F; f++)
        idx[f] = __ldg(sidx + (size_t)row * cfg::F + f);

    // first-order sparse gathers (lanes q and q+16 handle features)
    float lin = __ldg(lin_tables + (size_t)q * cfg::V + idx[q]);
    if (q < cfg::F - 16)
        lin += __ldg(lin_tables + (size_t)(q + 16) * cfg::V + idx[q + 16]);

    // dense embedding: de = dense @ Wd  (float4 slice per lane)
    float4 de = make_float4(0.f, 0.f, 0.f, 0.f);
#pragma unroll
    for (int i = 0; i < cfg::ND; i++) {
        float dv = dr[i];
        float4 w = __ldg(reinterpret_cast<const float4*>(
                             Wd + i * cfg::D) + q);
        de.x += dv * w.x; de.y += dv * w.y;
        de.z += dv * w.z; de.w += dv * w.w;
    }

    float4 s4  = de;
    float4 sq4 = make_float4(de.x * de.x, de.y * de.y,
                             de.z * de.z, de.w * de.w);

    uint32_t* hrow = reinterpret_cast<uint32_t*>(
        g_h + (size_t)row * cfg::K0) + q;
    hrow[0] = pack4_fp8(de.x * SCALE, de.y * SCALE,
                        de.z * SCALE, de.w * SCALE);

#pragma unroll
    for (int f = 0; f < cfg::F; f++) {
        float4 e = __ldg(reinterpret_cast<const float4*>(
                             emb_tables + ((size_t)f * cfg::V + idx[f]) *
                                              cfg::D) + q);
        s4.x += e.x;  s4.y += e.y;  s4.z += e.z;  s4.w += e.w;
        sq4.x += e.x * e.x; sq4.y += e.y * e.y;
        sq4.z += e.z * e.z; sq4.w += e.w * e.w;
        hrow[(f + 1) * (cfg::D / 4)] =
            pack4_fp8(e.x * SCALE, e.y * SCALE, e.z * SCALE, e.w * SCALE);
    }

    float val = 0.5f * ((s4.x * s4.x - sq4.x) + (s4.y * s4.y - sq4.y) +
                        (s4.z * s4.z - sq4.z) + (s4.w * s4.w - sq4.w)) + lin;
    if (q < cfg::ND) val += dr[q] * Wld[q];

    // reduce across the 16 lanes of this row
#pragma unroll
    for (int o = 8; o > 0; o >>= 1)
        val += __shfl_down_sync(0xffffffffu, val, o, 16);
    if (q == 0)
        out[row] = bias[0] + bld[0] + val;
}

// ------------------------- FP8 tensor-core GEMM (R11 verbatim) -------------
#define BM 128
#define BN 128
#define BK 64
#define NS 4
#define TSTR 80                     // 64B row + 16B pad (conflict-free)
#define A_ST (BM * TSTR)            // 10240 B / stage
#define B_ST (BN * TSTR)            // 10240 B / stage
#define STAGE_B (A_ST + B_ST)
#define GEMM_SMEM (NS * STAGE_B)    // 81920 B

__device__ __forceinline__ uint32_t smem_u32(const void* p) {
    return (uint32_t)__cvta_generic_to_shared(p);
}
__device__ __forceinline__ void cp16(uint32_t s, const void* g) {
    asm volatile("cp.async.cg.shared.global [%0], [%1], 16;\n" ::"r"(s), "l"(g));
}
__device__ __forceinline__ void cp_commit() {
    asm volatile("cp.async.commit_group;\n");
}
template <int N> __device__ __forceinline__ void cp_wait() {
    asm volatile("cp.async.wait_group %0;\n" ::"n"(N));
}
__device__ __forceinline__ void ldm_x4(uint32_t a, uint32_t& r0, uint32_t& r1,
                                       uint32_t& r2, uint32_t& r3) {
    asm volatile("ldmatrix.sync.aligned.m8n8.x4.shared.b16 {%0,%1,%2,%3}, [%4];\n"
                 : "=r"(r0), "=r"(r1), "=r"(r2), "=r"(r3)
                 : "r"(a));
}
__device__ __forceinline__ void mma_fp8(float* c, const uint32_t* a,
                                        uint32_t b0, uint32_t b1) {
    asm volatile(
        "mma.sync.aligned.m16n8k32.row.col.f32.e4m3.e4m3.f32 "
        "{%0,%1,%2,%3}, {%4,%5,%6,%7}, {%8,%9}, {%0,%1,%2,%3};\n"
        : "+f"(c[0]), "+f"(c[1]), "+f"(c[2]), "+f"(c[3])
        : "r"(a[0]), "r"(a[1]), "r"(a[2]), "r"(a[3]), "r"(b0), "r"(b1));
}

// MODE 0: C = fp8(relu(acc)/64).  MODE 1: out[m] += relu(acc)@Wout/4096.
template <int MODE>
__global__ __launch_bounds__(256, 2) void gemm_relu_fp8(
    const uint8_t* __restrict__ A, const uint8_t* __restrict__ Wt,
    uint8_t* __restrict__ C, const float* __restrict__ Wout,
    float* __restrict__ out, int M, int N, int K)
{
    extern __shared__ __align__(16) uint8_t smem[];

    const int tid  = threadIdx.x;
    const int bm   = blockIdx.y * BM;
    const int bn   = blockIdx.x * BN;
    const int wid  = tid >> 5;
    const int lane = tid & 31;
    const int wm   = (wid & 3) * 32;   // 4 warps over M
    const int wn   = (wid >> 2) * 64;  // 2 warps over N

    const int r0  = tid >> 2;           // 0..63
    const int cg0 = (tid & 3) * 16;     // 0/16/32/48
    const uint8_t* pA = A  + (size_t)(bm + r0) * K + cg0;
    const uint8_t* pB = Wt + (size_t)(bn + r0) * K + cg0;
    const size_t rowstep = (size_t)64 * K;    // +64 rows
    const uint32_t sbase = smem_u32(smem);
    const uint32_t sAoff = sbase + r0 * TSTR + cg0;
    const uint32_t sBoff = sAoff + A_ST;

    auto load_tiles = [&](int buf, const uint8_t* a, const uint8_t* b) {
        const uint32_t so = buf * STAGE_B;
        cp16(sAoff + so,             a);
        cp16(sAoff + so + 64 * TSTR, a + rowstep);
        cp16(sBoff + so,             b);
        cp16(sBoff + so + 64 * TSTR, b + rowstep);
    };

    const uint32_t aBase = sbase + (wm + (lane & 15)) * TSTR +
                           (lane >> 4) * 16;
    const uint32_t bBase = sbase + A_ST + (wn + (lane & 15)) * TSTR +
                           (lane >> 4) * 16;

    float acc[2][8][4];
#pragma unroll
    for (int i = 0; i < 2; i++)
#pragma unroll
        for (int j = 0; j < 8; j++)
#pragma unroll
            for (int k = 0; k < 4; k++) acc[i][j][k] = 0.f;

    const int KT = K / BK;

#pragma unroll
    for (int s = 0; s < NS - 1; s++) {
        load_tiles(s, pA, pB);
        pA += BK;
        pB += BK;
        cp_commit();
    }

    for (int kt = 0; kt < KT; kt++) {
        const int buf = kt % NS;
        cp_wait<NS - 2>();
        __syncthreads();

        if (kt + NS - 1 < KT) {
            load_tiles((kt + NS - 1) % NS, pA, pB);
            pA += BK;
            pB += BK;
        }
        cp_commit();

        const uint32_t so = buf * STAGE_B;

        uint32_t af[2][2][4], bf[2][4][4];
#pragma unroll
        for (int ks = 0; ks < 2; ks++) {
            const uint32_t kso = so + ks * 32;
#pragma unroll
            for (int mi = 0; mi < 2; mi++)
                ldm_x4(aBase + kso + mi * (16 * TSTR),
                       af[ks][mi][0], af[ks][mi][1],
                       af[ks][mi][2], af[ks][mi][3]);
#pragma unroll
            for (int nj = 0; nj < 4; nj++)
                ldm_x4(bBase + kso + nj * (16 * TSTR),
                       bf[ks][nj][0], bf[ks][nj][1],
                       bf[ks][nj][2], bf[ks][nj][3]);
        }
#pragma unroll
        for (int ks = 0; ks < 2; ks++)
#pragma unroll
            for (int mi = 0; mi < 2; mi++)
#pragma unroll
                for (int nj = 0; nj < 4; nj++) {
                    mma_fp8(acc[mi][nj * 2],     af[ks][mi],
                            bf[ks][nj][0], bf[ks][nj][2]);
                    mma_fp8(acc[mi][nj * 2 + 1], af[ks][mi],
                            bf[ks][nj][1], bf[ks][nj][3]);
                }
    }

    const int lr = lane >> 2, lc = (lane & 3) * 2;
    if (MODE == 1) {
#pragma unroll
        for (int mi = 0; mi < 2; mi++) {
            float s0 = 0.f, s1 = 0.f;
#pragma unroll
            for (int ni = 0; ni < 8; ni++) {
                int n0 = bn + wn + ni * 8 + lc;
                float w0 = __ldg(Wout + n0);
                float w1 = __ldg(Wout + n0 + 1);
                s0 += fmaxf(acc[mi][ni][0], 0.f) * w0 +
                      fmaxf(acc[mi][ni][1], 0.f) * w1;
                s1 += fmaxf(acc[mi][ni][2], 0.f) * w0 +
                      fmaxf(acc[mi][ni][3], 0.f) * w1;
            }
            s0 += __shfl_xor_sync(0xffffffffu, s0, 1);
            s0 += __shfl_xor_sync(0xffffffffu, s0, 2);
            s1 += __shfl_xor_sync(0xffffffffu, s1, 1);
            s1 += __shfl_xor_sync(0xffffffffu, s1, 2);
            if ((lane & 3) == 0) {
                int m0 = bm + wm + mi * 16 + lr;
                atomicAdd(out + m0,     s0 * INV_SCALE2);
                atomicAdd(out + m0 + 8, s1 * INV_SCALE2);
            }
        }
    } else {
#pragma unroll
        for (int mi = 0; mi < 2; mi++)
#pragma unroll
            for (int ni = 0; ni < 8; ni++) {
                int m0 = bm + wm + mi * 16 + lr;
                int n0 = bn + wn + ni * 8 + lc;
                float v0 = fmaxf(acc[mi][ni][0], 0.f) * INV_SCALE;
                float v1 = fmaxf(acc[mi][ni][1], 0.f) * INV_SCALE;
                float v2 = fmaxf(acc[mi][ni][2], 0.f) * INV_SCALE;
                float v3 = fmaxf(acc[mi][ni][3], 0.f) * INV_SCALE;
                *reinterpret_cast<unsigned short*>(C + (size_t)m0 * N + n0) =
                    (unsigned short)__nv_cvt_float2_to_fp8x2(
                        make_float2(v0, v1), __NV_SATFINITE, __NV_E4M3);
                *reinterpret_cast<unsigned short*>(C + (size_t)(m0 + 8) * N + n0) =
                    (unsigned short)__nv_cvt_float2_to_fp8x2(
                        make_float2(v2, v3), __NV_SATFINITE, __NV_E4M3);
            }
    }
}

// ------------------------- launch ------------------------------------------
extern "C" void kernel_launch(void* const* d_in, const int* in_sizes, int n_in,
                              void* d_out, int out_size) {
    const float* dense = (const float*)d_in[0];
    const int*   sidx  = (const int*)d_in[1];
    const float* bias  = (const float*)d_in[2];
    const float* emb   = (const float*)d_in[3];
    const float* lin   = (const float*)d_in[4];
    const float* Wd    = (const float*)d_in[5];
    const float* Wld   = (const float*)d_in[6];
    const float* bld   = (const float*)d_in[7];
    const float* W1    = (const float*)d_in[8];
    const float* W2    = (const float*)d_in[9];
    const float* W3    = (const float*)d_in[10];
    const float* Wout  = (const float*)d_in[11];
    float* out = (float*)d_out;

    void *p_h, *p_h1, *p_h2, *p_W1, *p_W2, *p_W3;
    cudaGetSymbolAddress(&p_h,  g_h);
    cudaGetSymbolAddress(&p_h1, g_h1);
    cudaGetSymbolAddress(&p_h2, g_h2);
    cudaGetSymbolAddress(&p_W1, g_Wt1);
    cudaGetSymbolAddress(&p_W2, g_Wt2);
    cudaGetSymbolAddress(&p_W3, g_Wt3);

    static bool init_done = false;
    static cudaStream_t s2;
    static cudaEvent_t evFork, evJoin;
    if (!init_done) {
        cudaFuncSetAttribute(gemm_relu_fp8<0>,
                             cudaFuncAttributeMaxDynamicSharedMemorySize,
                             GEMM_SMEM);
        cudaFuncSetAttribute(gemm_relu_fp8<1>,
                             cudaFuncAttributeMaxDynamicSharedMemorySize,
                             GEMM_SMEM);
        cudaStreamCreateWithFlags(&s2, cudaStreamNonBlocking);
        cudaEventCreateWithFlags(&evFork, cudaEventDisableTiming);
        cudaEventCreateWithFlags(&evJoin, cudaEventDisableTiming);
        init_done = true;
    }

    // fork: weight convert overlaps with embed
    cudaEventRecord(evFork, 0);
    cudaStreamWaitEvent(s2, evFork, 0);
    transpose_convert_all<<<dim3(cfg::H1 / 32, cfg::K0 / 32, 3), 256, 0, s2>>>(
        W1, W2, W3);
    cudaEventRecord(evJoin, s2);

    embed_kernel<<<cfg::B / 16, 256>>>(dense, sidx, bias, emb, lin, Wd, Wld,
                                       bld, out);

    // join before GEMMs consume converted weights
    cudaStreamWaitEvent(0, evJoin, 0);

    dim3 g1(cfg::H1 / BN, cfg::B / BM);
    gemm_relu_fp8<0><<<g1, 256, GEMM_SMEM>>>(
        (const uint8_t*)p_h, (const uint8_t*)p_W1, (uint8_t*)p_h1,
        nullptr, nullptr, cfg::B, cfg::H1, cfg::K0);
    dim3 g2(cfg::H2 / BN, cfg::B / BM);
    gemm_relu_fp8<0><<<g2, 256, GEMM_SMEM>>>(
        (const uint8_t*)p_h1, (const uint8_t*)p_W2, (uint8_t*)p_h2,
        nullptr, nullptr, cfg::B, cfg::H2, cfg::H1);
    dim3 g3(cfg::H3 / BN, cfg::B / BM);
    gemm_relu_fp8<1><<<g3, 256, GEMM_SMEM>>>(
        (const uint8_t*)p_h2, (const uint8_t*)p_W3, nullptr,
        Wout, out, cfg::B, cfg::H3, cfg::H2);
}

// round 15
// speedup vs baseline: 1.4840x; 1.0848x over previous
#include <cuda_runtime.h>
#include <cuda_bf16.h>
#include <cuda_fp8.h>
#include <cstdint>

// ---------------------------------------------------------------------------
// DeepFM: out = bias + first + second + MLP(emb)
// GEMM core = R11 champion (fp8 e4m3 mma.sync, CTA 128x128, BK=64, NS=4,
// 256 thr, 2 CTA/SM). R15: batch split in 2 halves on 2 streams, each
// running embed -> G1 -> G2 -> G3; weight-convert on a 3rd stream.
// Embed (memory-bound) overlaps GEMM (tensor-bound) across halves.
// Scaling: act/weights fp8 of (value*64); acc = 4096*true. FM terms fp32.
// ---------------------------------------------------------------------------

namespace cfg {
constexpr int B  = 16384;
constexpr int F  = 26;
constexpr int V  = 100000;
constexpr int D  = 64;
constexpr int ND = 13;
constexpr int H1 = 1024;
constexpr int H2 = 512;
constexpr int H3 = 256;
constexpr int K0 = (F + 1) * D;   // 1728
constexpr int BH = B / 2;         // rows per half
}

constexpr float SCALE = 64.f;
constexpr float INV_SCALE = 1.f / 64.f;
constexpr float INV_SCALE2 = 1.f / 4096.f;

// ------------------------- scratch (device globals) ------------------------
__device__ uint8_t g_h  [(size_t)cfg::B * cfg::K0];   // fp8 e4m3, x64
__device__ uint8_t g_h1 [(size_t)cfg::B * cfg::H1];
__device__ uint8_t g_h2 [(size_t)cfg::B * cfg::H2];
__device__ uint8_t g_Wt1[cfg::H1 * cfg::K0];          // [N,K] fp8, x64
__device__ uint8_t g_Wt2[cfg::H2 * cfg::H1];
__device__ uint8_t g_Wt3[cfg::H3 * cfg::H2];

__device__ __forceinline__ uint8_t to_fp8(float v) {
    return (uint8_t)__nv_cvt_float_to_fp8(v, __NV_SATFINITE, __NV_E4M3);
}

// ------------------------- fused weight transpose+convert ------------------
__global__ __launch_bounds__(256) void transpose_convert_all(
    const float* __restrict__ W1, const float* __restrict__ W2,
    const float* __restrict__ W3) {
    const float* in;
    uint8_t* out;
    int K, N;
    if (blockIdx.z == 0)      { in = W1; out = g_Wt1; K = cfg::K0; N = cfg::H1; }
    else if (blockIdx.z == 1) { in = W2; out = g_Wt2; K = cfg::H1; N = cfg::H2; }
    else                      { in = W3; out = g_Wt3; K = cfg::H2; N = cfg::H3; }

    const int n0 = blockIdx.x * 32, k0 = blockIdx.y * 32;
    if (n0 >= N || k0 >= K) return;

    __shared__ float t[32][33];
    const int tx = threadIdx.x & 31, ty = threadIdx.x >> 5;  // 32x8
#pragma unroll
    for (int j = 0; j < 4; j++)
        t[ty + j * 8][tx] = in[(size_t)(k0 + ty + j * 8) * N + n0 + tx];
    __syncthreads();
#pragma unroll
    for (int j = 0; j < 4; j++)
        out[(size_t)(n0 + ty + j * 8) * K + k0 + tx] =
            to_fp8(t[tx][ty + j * 8] * SCALE);
}

// ------------------------- embed + FM (fp32 exact, R11 layout) -------------
// Pointers pre-offset by the caller for each batch half.
__global__ __launch_bounds__(256) void embed_kernel(
    const float* __restrict__ dense, const int* __restrict__ sidx,
    const float* __restrict__ bias, const float* __restrict__ emb_tables,
    const float* __restrict__ lin_tables, const float* __restrict__ Wd,
    const float* __restrict__ Wld, const float* __restrict__ bld,
    uint8_t* __restrict__ hout, float* __restrict__ out) {
    const int sub = threadIdx.x >> 6;
    const int d   = threadIdx.x & 63;
    const int row = blockIdx.x * 4 + sub;

    const float* dr = dense + (size_t)row * cfg::ND;

    int idx[cfg::F];
#pragma unroll
    for (int f = 0; f < cfg::F; f++) idx[f] = __ldg(sidx + (size_t)row * cfg::F + f);

    float ev[cfg::F];
#pragma unroll
    for (int f = 0; f < cfg::F; f++)
        ev[f] = __ldg(emb_tables + ((size_t)f * cfg::V + idx[f]) * cfg::D + d);

    float lin = 0.f;
    if (d < cfg::F) lin = __ldg(lin_tables + (size_t)d * cfg::V + idx[d]);

    float de = 0.f;
#pragma unroll
    for (int i = 0; i < cfg::ND; i++) de += dr[i] * Wd[i * cfg::D + d];

    float s  = de;
    float sq = de * de;
    uint8_t* hrow = hout + (size_t)row * cfg::K0;
    hrow[d] = to_fp8(de * SCALE);

#pragma unroll
    for (int f = 0; f < cfg::F; f++) {
        float e = ev[f];
        s  += e;
        sq += e * e;
        hrow[(size_t)(f + 1) * cfg::D + d] = to_fp8(e * SCALE);
    }

    float val = 0.5f * (s * s - sq) + lin;
    if (d < cfg::ND) val += dr[d] * Wld[d];

#pragma unroll
    for (int o = 16; o > 0; o >>= 1)
        val += __shfl_down_sync(0xffffffffu, val, o);

    __shared__ float red[8];
    if ((threadIdx.x & 31) == 0) red[threadIdx.x >> 5] = val;
    __syncthreads();
    if (d == 0)
        out[row] = bias[0] + bld[0] + red[sub * 2] + red[sub * 2 + 1];
}

// ------------------------- FP8 tensor-core GEMM (R11 core) -----------------
#define BM 128
#define BN 128
#define BK 64
#define NS 4
#define TSTR 80                     // 64B row + 16B pad (conflict-free)
#define A_ST (BM * TSTR)            // 10240 B / stage
#define B_ST (BN * TSTR)            // 10240 B / stage
#define STAGE_B (A_ST + B_ST)
#define GEMM_SMEM (NS * STAGE_B)    // 81920 B

__device__ __forceinline__ uint32_t smem_u32(const void* p) {
    return (uint32_t)__cvta_generic_to_shared(p);
}
__device__ __forceinline__ void cp16(uint32_t s, const void* g) {
    asm volatile("cp.async.cg.shared.global [%0], [%1], 16;\n" ::"r"(s), "l"(g));
}
__device__ __forceinline__ void cp_commit() {
    asm volatile("cp.async.commit_group;\n");
}
template <int N> __device__ __forceinline__ void cp_wait() {
    asm volatile("cp.async.wait_group %0;\n" ::"n"(N));
}
__device__ __forceinline__ void ldm_x4(uint32_t a, uint32_t& r0, uint32_t& r1,
                                       uint32_t& r2, uint32_t& r3) {
    asm volatile("ldmatrix.sync.aligned.m8n8.x4.shared.b16 {%0,%1,%2,%3}, [%4];\n"
                 : "=r"(r0), "=r"(r1), "=r"(r2), "=r"(r3)
                 : "r"(a));
}
__device__ __forceinline__ void mma_fp8(float* c, const uint32_t* a,
                                        uint32_t b0, uint32_t b1) {
    asm volatile(
        "mma.sync.aligned.m16n8k32.row.col.f32.e4m3.e4m3.f32 "
        "{%0,%1,%2,%3}, {%4,%5,%6,%7}, {%8,%9}, {%0,%1,%2,%3};\n"
        : "+f"(c[0]), "+f"(c[1]), "+f"(c[2]), "+f"(c[3])
        : "r"(a[0]), "r"(a[1]), "r"(a[2]), "r"(a[3]), "r"(b0), "r"(b1));
}

// MODE 0: C = fp8(relu(acc)/64).  MODE 1: out[m] += relu(acc)@Wout/4096.
template <int MODE>
__global__ __launch_bounds__(256, 2) void gemm_relu_fp8(
    const uint8_t* __restrict__ A, const uint8_t* __restrict__ Wt,
    uint8_t* __restrict__ C, const float* __restrict__ Wout,
    float* __restrict__ out, int M, int N, int K)
{
    extern __shared__ __align__(16) uint8_t smem[];

    const int tid  = threadIdx.x;
    const int bm   = blockIdx.y * BM;
    const int bn   = blockIdx.x * BN;
    const int wid  = tid >> 5;
    const int lane = tid & 31;
    const int wm   = (wid & 3) * 32;   // 4 warps over M
    const int wn   = (wid >> 2) * 64;  // 2 warps over N

    const int r0  = tid >> 2;           // 0..63
    const int cg0 = (tid & 3) * 16;     // 0/16/32/48
    const uint8_t* pA = A  + (size_t)(bm + r0) * K + cg0;
    const uint8_t* pB = Wt + (size_t)(bn + r0) * K + cg0;
    const size_t rowstep = (size_t)64 * K;    // +64 rows
    const uint32_t sbase = smem_u32(smem);
    const uint32_t sAoff = sbase + r0 * TSTR + cg0;
    const uint32_t sBoff = sAoff + A_ST;

    auto load_tiles = [&](int buf, const uint8_t* a, const uint8_t* b) {
        const uint32_t so = buf * STAGE_B;
        cp16(sAoff + so,             a);
        cp16(sAoff + so + 64 * TSTR, a + rowstep);
        cp16(sBoff + so,             b);
        cp16(sBoff + so + 64 * TSTR, b + rowstep);
    };

    const uint32_t aBase = sbase + (wm + (lane & 15)) * TSTR +
                           (lane >> 4) * 16;
    const uint32_t bBase = sbase + A_ST + (wn + (lane & 15)) * TSTR +
                           (lane >> 4) * 16;

    float acc[2][8][4];
#pragma unroll
    for (int i = 0; i < 2; i++)
#pragma unroll
        for (int j = 0; j < 8; j++)
#pragma unroll
            for (int k = 0; k < 4; k++) acc[i][j][k] = 0.f;

    const int KT = K / BK;

#pragma unroll
    for (int s = 0; s < NS - 1; s++) {
        load_tiles(s, pA, pB);
        pA += BK;
        pB += BK;
        cp_commit();
    }

    for (int kt = 0; kt < KT; kt++) {
        const int buf = kt % NS;
        cp_wait<NS - 2>();
        __syncthreads();

        if (kt + NS - 1 < KT) {
            load_tiles((kt + NS - 1) % NS, pA, pB);
            pA += BK;
            pB += BK;
        }
        cp_commit();

        const uint32_t so = buf * STAGE_B;

        uint32_t af[2][2][4], bf[2][4][4];
#pragma unroll
        for (int ks = 0; ks < 2; ks++) {
            const uint32_t kso = so + ks * 32;
#pragma unroll
            for (int mi = 0; mi < 2; mi++)
                ldm_x4(aBase + kso + mi * (16 * TSTR),
                       af[ks][mi][0], af[ks][mi][1],
                       af[ks][mi][2], af[ks][mi][3]);
#pragma unroll
            for (int nj = 0; nj < 4; nj++)
                ldm_x4(bBase + kso + nj * (16 * TSTR),
                       bf[ks][nj][0], bf[ks][nj][1],
                       bf[ks][nj][2], bf[ks][nj][3]);
        }
#pragma unroll
        for (int ks = 0; ks < 2; ks++)
#pragma unroll
            for (int mi = 0; mi < 2; mi++)
#pragma unroll
                for (int nj = 0; nj < 4; nj++) {
                    mma_fp8(acc[mi][nj * 2],     af[ks][mi],
                            bf[ks][nj][0], bf[ks][nj][2]);
                    mma_fp8(acc[mi][nj * 2 + 1], af[ks][mi],
                            bf[ks][nj][1], bf[ks][nj][3]);
                }
    }

    const int lr = lane >> 2, lc = (lane & 3) * 2;
    if (MODE == 1) {
#pragma unroll
        for (int mi = 0; mi < 2; mi++) {
            float s0 = 0.f, s1 = 0.f;
#pragma unroll
            for (int ni = 0; ni < 8; ni++) {
                int n0 = bn + wn + ni * 8 + lc;
                float w0 = __ldg(Wout + n0);
                float w1 = __ldg(Wout + n0 + 1);
                s0 += fmaxf(acc[mi][ni][0], 0.f) * w0 +
                      fmaxf(acc[mi][ni][1], 0.f) * w1;
                s1 += fmaxf(acc[mi][ni][2], 0.f) * w0 +
                      fmaxf(acc[mi][ni][3], 0.f) * w1;
            }
            s0 += __shfl_xor_sync(0xffffffffu, s0, 1);
            s0 += __shfl_xor_sync(0xffffffffu, s0, 2);
            s1 += __shfl_xor_sync(0xffffffffu, s1, 1);
            s1 += __shfl_xor_sync(0xffffffffu, s1, 2);
            if ((lane & 3) == 0) {
                int m0 = bm + wm + mi * 16 + lr;
                atomicAdd(out + m0,     s0 * INV_SCALE2);
                atomicAdd(out + m0 + 8, s1 * INV_SCALE2);
            }
        }
    } else {
#pragma unroll
        for (int mi = 0; mi < 2; mi++)
#pragma unroll
            for (int ni = 0; ni < 8; ni++) {
                int m0 = bm + wm + mi * 16 + lr;
                int n0 = bn + wn + ni * 8 + lc;
                float v0 = fmaxf(acc[mi][ni][0], 0.f) * INV_SCALE;
                float v1 = fmaxf(acc[mi][ni][1], 0.f) * INV_SCALE;
                float v2 = fmaxf(acc[mi][ni][2], 0.f) * INV_SCALE;
                float v3 = fmaxf(acc[mi][ni][3], 0.f) * INV_SCALE;
                *reinterpret_cast<unsigned short*>(C + (size_t)m0 * N + n0) =
                    (unsigned short)__nv_cvt_float2_to_fp8x2(
                        make_float2(v0, v1), __NV_SATFINITE, __NV_E4M3);
                *reinterpret_cast<unsigned short*>(C + (size_t)(m0 + 8) * N + n0) =
                    (unsigned short)__nv_cvt_float2_to_fp8x2(
                        make_float2(v2, v3), __NV_SATFINITE, __NV_E4M3);
            }
    }
}

// ------------------------- launch ------------------------------------------
extern "C" void kernel_launch(void* const* d_in, const int* in_sizes, int n_in,
                              void* d_out, int out_size) {
    const float* dense = (const float*)d_in[0];
    const int*   sidx  = (const int*)d_in[1];
    const float* bias  = (const float*)d_in[2];
    const float* emb   = (const float*)d_in[3];
    const float* lin   = (const float*)d_in[4];
    const float* Wd    = (const float*)d_in[5];
    const float* Wld   = (const float*)d_in[6];
    const float* bld   = (const float*)d_in[7];
    const float* W1    = (const float*)d_in[8];
    const float* W2    = (const float*)d_in[9];
    const float* W3    = (const float*)d_in[10];
    const float* Wout  = (const float*)d_in[11];
    float* out = (float*)d_out;

    void *p_h, *p_h1, *p_h2, *p_W1, *p_W2, *p_W3;
    cudaGetSymbolAddress(&p_h,  g_h);
    cudaGetSymbolAddress(&p_h1, g_h1);
    cudaGetSymbolAddress(&p_h2, g_h2);
    cudaGetSymbolAddress(&p_W1, g_Wt1);
    cudaGetSymbolAddress(&p_W2, g_Wt2);
    cudaGetSymbolAddress(&p_W3, g_Wt3);

    static bool init_done = false;
    static cudaStream_t sB, sC;              // half-1 stream, convert stream
    static cudaEvent_t evFork, evConv, evB;
    if (!init_done) {
        cudaFuncSetAttribute(gemm_relu_fp8<0>,
                             cudaFuncAttributeMaxDynamicSharedMemorySize,
                             GEMM_SMEM);
        cudaFuncSetAttribute(gemm_relu_fp8<1>,
                             cudaFuncAttributeMaxDynamicSharedMemorySize,
                             GEMM_SMEM);
        cudaStreamCreateWithFlags(&sB, cudaStreamNonBlocking);
        cudaStreamCreateWithFlags(&sC, cudaStreamNonBlocking);
        cudaEventCreateWithFlags(&evFork, cudaEventDisableTiming);
        cudaEventCreateWithFlags(&evConv, cudaEventDisableTiming);
        cudaEventCreateWithFlags(&evB, cudaEventDisableTiming);
        init_done = true;
    }

    // fork
    cudaEventRecord(evFork, 0);
    cudaStreamWaitEvent(sB, evFork, 0);
    cudaStreamWaitEvent(sC, evFork, 0);

    // weight convert on sC
    transpose_convert_all<<<dim3(cfg::H1 / 32, cfg::K0 / 32, 3), 256, 0, sC>>>(
        W1, W2, W3);
    cudaEventRecord(evConv, sC);

    // per-half pipelines
    const int halves = 2;
    cudaStream_t streams[2] = {(cudaStream_t)0, sB};
    for (int hfi = 0; hfi < halves; hfi++) {
        cudaStream_t st = streams[hfi];
        const size_t off = (size_t)hfi * cfg::BH;
        uint8_t* ph  = (uint8_t*)p_h  + off * cfg::K0;
        uint8_t* ph1 = (uint8_t*)p_h1 + off * cfg::H1;
        uint8_t* ph2 = (uint8_t*)p_h2 + off * cfg::H2;
        float*   po  = out + off;

        embed_kernel<<<cfg::BH / 4, 256, 0, st>>>(
            dense + off * cfg::ND, sidx + off * cfg::F, bias, emb, lin,
            Wd, Wld, bld, ph, po);

        cudaStreamWaitEvent(st, evConv, 0);   // weights ready

        dim3 g1(cfg::H1 / BN, cfg::BH / BM);
        gemm_relu_fp8<0><<<g1, 256, GEMM_SMEM, st>>>(
            ph, (const uint8_t*)p_W1, ph1, nullptr, nullptr,
            cfg::BH, cfg::H1, cfg::K0);
        dim3 g2(cfg::H2 / BN, cfg::BH / BM);
        gemm_relu_fp8<0><<<g2, 256, GEMM_SMEM, st>>>(
            ph1, (const uint8_t*)p_W2, ph2, nullptr, nullptr,
            cfg::BH, cfg::H2, cfg::H1);
        dim3 g3(cfg::H3 / BN, cfg::BH / BM);
        gemm_relu_fp8<1><<<g3, 256, GEMM_SMEM, st>>>(
            ph2, (const uint8_t*)p_W3, nullptr, Wout, po,
            cfg::BH, cfg::H3, cfg::H2);
    }

    // join half-1 back into the main stream
    cudaEventRecord(evB, sB);
    cudaStreamWaitEvent(0, evB, 0);
}